// round 4
// baseline (speedup 1.0000x reference)
#include <cuda_runtime.h>
#include <cuda_bf16.h>
#include <cstdint>

#define NN 50000
#define EE 800000
#define DD 128
#define TILES ((NN + 127) / 128)       // 391
#define PADROWS (TILES * 128)          // 50048
#define CSR_BLOCKS ((EE + 255) / 256)  // 3125
#define SCALE_BLOCKS ((NN * 32 + 255) / 256)

// ---------------- scratch (static device globals; no allocation) ----------
__device__ float    g_y[NN * DD];       // y0 = dinv .* x  (layer-0 agg input)
__device__ float    g_h[NN * DD];       // y1 = dinv .* relu(layer0 out)
__device__ uint32_t g_ap[PADROWS * DD]; // agg out, packed bf16 (hi,lo) interleaved
__device__ int      g_csr_src[EE];
__device__ int      g_deg[NN];
__device__ int      g_off[NN + 1];
__device__ int      g_cur[NN];
__device__ float    g_dinv[NN];
__device__ int      g_is64;
// W packed in mma.m16n8k16 B-fragment order, bf16 hi/lo
__device__ uint32_t g_bp_hi[2 * 8 * 16 * 64];
__device__ uint32_t g_bp_lo[2 * 8 * 16 * 64];

// ---------------- fused: zero counters + dtype detect + W pack -------------
__global__ void k_pre(const int* __restrict__ raw, const float* __restrict__ W) {
    int idx = blockIdx.x * blockDim.x + threadIdx.x;
    if (idx < NN) { g_deg[idx] = 0; g_cur[idx] = 0; }
    if (idx < 2 * DD * DD) {
        int l = idx >> 14;
        int r = idx & 16383;
        int k = r >> 7;    // K index (in-dim)
        int n = r & 127;   // N index (out-dim)
        float v = W[l * DD * DD + k * DD + n];
        __nv_bfloat16 h  = __float2bfloat16(v);
        __nv_bfloat16 lo = __float2bfloat16(v - __bfloat162float(h));
        int ks = k >> 4, kk = k & 15;
        int reg = kk >> 3, k8 = kk & 7;
        int lane = ((n & 7) << 2) | (k8 >> 1);
        int i    = k8 & 1;
        int nt   = n >> 3;
        size_t u32i = ((((size_t)l * 8 + ks) * 16 + nt) * 64) + (size_t)lane * 2 + reg;
        ((unsigned short*)g_bp_hi)[u32i * 2 + i] = __bfloat16_as_ushort(h);
        ((unsigned short*)g_bp_lo)[u32i * 2 + i] = __bfloat16_as_ushort(lo);
    }
    if (blockIdx.x == 0) {
        __shared__ int found;
        if (threadIdx.x == 0) found = 0;
        __syncthreads();
        for (int j = threadIdx.x; j < 2048; j += blockDim.x)
            if (raw[2 * j + 1] != 0) found = 1;
        __syncthreads();
        if (threadIdx.x == 0) g_is64 = found ? 0 : 1;
    }
}

__device__ __forceinline__ void load_edge(const void* raw, int e, int is64,
                                          int& s, int& d) {
    if (is64) {
        const long long* p = (const long long*)raw;
        s = (int)p[e];
        d = (int)p[EE + e];
    } else {
        const int* p = (const int*)raw;
        s = p[e];
        d = p[EE + e];
    }
}

__global__ void k_deg(const void* __restrict__ raw) {
    int e = blockIdx.x * blockDim.x + threadIdx.x;
    if (e >= EE) return;
    int d;
    if (g_is64) d = (int)((const long long*)raw)[EE + e];
    else        d = ((const int*)raw)[EE + e];
    atomicAdd(&g_deg[d], 1);
}

// single-block scan of g_deg -> g_off; also computes g_dinv
__global__ void k_scan() {
    const int T = 1024;
    const int ITEMS = (NN + T - 1) / T;  // 49
    __shared__ int sm[T];
    int t = threadIdx.x;
    int base = t * ITEMS;
    int sum = 0;
    for (int j = 0; j < ITEMS; ++j) {
        int idx = base + j;
        if (idx < NN) sum += g_deg[idx];
    }
    sm[t] = sum;
    __syncthreads();
    for (int dstep = 1; dstep < T; dstep <<= 1) {
        int v = (t >= dstep) ? sm[t - dstep] : 0;
        __syncthreads();
        sm[t] += v;
        __syncthreads();
    }
    int run = sm[t] - sum;
    for (int j = 0; j < ITEMS; ++j) {
        int idx = base + j;
        if (idx < NN) {
            int dg = g_deg[idx];
            g_off[idx] = run;
            g_dinv[idx] = rsqrtf((float)dg + 1.0f);
            run += dg;
        }
    }
    if (t == T - 1) g_off[NN] = sm[T - 1];
}

// ---------------- fused: CSR scatter (src only) + y0 = dinv .* x -----------
__global__ void k_csr_scale(const void* __restrict__ raw,
                            const float* __restrict__ x) {
    int b = blockIdx.x;
    if (b < CSR_BLOCKS) {
        int e = b * 256 + threadIdx.x;
        if (e < EE) {
            int is64 = g_is64;
            int s, d;
            load_edge(raw, e, is64, s, d);
            int p = g_off[d] + atomicAdd(&g_cur[d], 1);
            g_csr_src[p] = s;
        }
    } else {
        int i = (b - CSR_BLOCKS) * 256 + threadIdx.x;
        if (i < NN * 32) {
            int row = i >> 5, l = i & 31;
            float di = g_dinv[row];
            float4 v = ((const float4*)(x + (size_t)row * DD))[l];
            v.x *= di; v.y *= di; v.z *= di; v.w *= di;
            ((float4*)(g_y + (size_t)row * DD))[l] = v;
        }
    }
}

// ---------------- aggregation: warp per node, batched gather ---------------
// out[d] = dinv[d] * (y[d] + sum y[s]); writes packed bf16 (hi,lo) to g_ap
__global__ void k_agg(int use_internal) {
    int gw   = (blockIdx.x * blockDim.x + threadIdx.x) >> 5;
    int lane = threadIdx.x & 31;
    if (gw >= NN) return;
    const float* __restrict__ y = use_internal ? g_h : g_y;

    float4 acc = ((const float4*)(y + (size_t)gw * DD))[lane];  // self y[d]

    int beg = g_off[gw];
    int end = g_off[gw + 1];
    for (int e0 = beg; e0 < end; e0 += 32) {
        int m = end - e0;
        if (m > 32) m = 32;
        int s_all = (lane < m) ? g_csr_src[e0 + lane] : 0;
        int jb = 0;
        for (; jb + 8 <= m; jb += 8) {
            float4 v[8];
            #pragma unroll
            for (int j = 0; j < 8; ++j) {
                int sj = __shfl_sync(0xffffffffu, s_all, jb + j);
                v[j] = ((const float4*)(y + (size_t)sj * DD))[lane];
            }
            #pragma unroll
            for (int j = 0; j < 8; ++j) {
                acc.x += v[j].x; acc.y += v[j].y;
                acc.z += v[j].z; acc.w += v[j].w;
            }
        }
        for (; jb < m; ++jb) {
            int sj = __shfl_sync(0xffffffffu, s_all, jb);
            float4 v = ((const float4*)(y + (size_t)sj * DD))[lane];
            acc.x += v.x; acc.y += v.y; acc.z += v.z; acc.w += v.w;
        }
    }
    float di = g_dinv[gw];
    acc.x *= di; acc.y *= di; acc.z *= di; acc.w *= di;

    // pack to bf16 hi/lo, interleaved (hi, lo) per float-pair
    __nv_bfloat162 h01 = __floats2bfloat162_rn(acc.x, acc.y);
    __nv_bfloat162 h23 = __floats2bfloat162_rn(acc.z, acc.w);
    float rx = acc.x - __bfloat162float(__low2bfloat16(h01));
    float ry = acc.y - __bfloat162float(__high2bfloat16(h01));
    float rz = acc.z - __bfloat162float(__low2bfloat16(h23));
    float rw = acc.w - __bfloat162float(__high2bfloat16(h23));
    __nv_bfloat162 l01 = __floats2bfloat162_rn(rx, ry);
    __nv_bfloat162 l23 = __floats2bfloat162_rn(rz, rw);
    uint4 o;
    o.x = *(uint32_t*)&h01;  // hi of cols (4L, 4L+1)
    o.y = *(uint32_t*)&l01;  // lo of cols (4L, 4L+1)
    o.z = *(uint32_t*)&h23;  // hi of cols (4L+2, 4L+3)
    o.w = *(uint32_t*)&l23;  // lo
    *(uint4*)(g_ap + (size_t)gw * DD + 4 * lane) = o;
}

// ---------------- mma.sync GEMM: out = relu(agg @ W + b) [, * dinv] --------
__device__ __forceinline__ void mma16816(float* d, const uint32_t* a,
                                         const uint32_t b0, const uint32_t b1) {
    asm volatile(
        "mma.sync.aligned.m16n8k16.row.col.f32.bf16.bf16.f32 "
        "{%0,%1,%2,%3}, {%4,%5,%6,%7}, {%8,%9}, {%0,%1,%2,%3};"
        : "+f"(d[0]), "+f"(d[1]), "+f"(d[2]), "+f"(d[3])
        : "r"(a[0]), "r"(a[1]), "r"(a[2]), "r"(a[3]), "r"(b0), "r"(b1));
}

__global__ void __launch_bounds__(256)
k_gemm_mma(const float* __restrict__ bg, float* __restrict__ outext,
           int layer, int write_internal) {
    int tid  = threadIdx.x;
    int lane = tid & 31;
    int wid  = tid >> 5;
    int mbase = blockIdx.x * 128 + (wid & 3) * 32;  // warp's 32 rows
    int nbase = (wid >> 2) * 64;                    // warp's 64 cols

    float* __restrict__ outp = write_internal ? g_h : outext;

    int qrow = lane >> 2;
    int qcol = (lane & 3) * 2;
    int q    = lane & 3;

    float acc[2][8][4];
    #pragma unroll
    for (int mt = 0; mt < 2; ++mt)
        #pragma unroll
        for (int nt = 0; nt < 8; ++nt)
            #pragma unroll
            for (int j = 0; j < 4; ++j) acc[mt][nt][j] = 0.0f;

    const uint2* __restrict__ ap   = (const uint2*)g_ap;
    const uint2* __restrict__ bhiP = (const uint2*)g_bp_hi;
    const uint2* __restrict__ bloP = (const uint2*)g_bp_lo;

    #pragma unroll 2
    for (int ks = 0; ks < 8; ++ks) {
        // ---- A fragments: packed (hi,lo) uint2 loads, no conversion ----
        uint32_t ahi[2][4], alo[2][4];
        #pragma unroll
        for (int mt = 0; mt < 2; ++mt) {
            int r0 = mbase + mt * 16 + qrow;   // rows < PADROWS always valid
            int r1 = r0 + 8;
            uint2 v00 = ap[(size_t)r0 * 64 + ks * 8 + q];
            uint2 v10 = ap[(size_t)r1 * 64 + ks * 8 + q];
            uint2 v01 = ap[(size_t)r0 * 64 + ks * 8 + 4 + q];
            uint2 v11 = ap[(size_t)r1 * 64 + ks * 8 + 4 + q];
            ahi[mt][0] = v00.x; alo[mt][0] = v00.y;
            ahi[mt][1] = v10.x; alo[mt][1] = v10.y;
            ahi[mt][2] = v01.x; alo[mt][2] = v01.y;
            ahi[mt][3] = v11.x; alo[mt][3] = v11.y;
        }
        // ---- B fragments (pre-packed, contiguous per warp) ----
        int bbase = (((layer * 8 + ks) * 16 + (nbase >> 3)) * 32) + lane;
        uint2 bh[8], bl[8];
        #pragma unroll
        for (int nt = 0; nt < 8; ++nt) {
            bh[nt] = bhiP[bbase + nt * 32];
            bl[nt] = bloP[bbase + nt * 32];
        }
        // ---- 48 HMMA ----
        #pragma unroll
        for (int mt = 0; mt < 2; ++mt)
            #pragma unroll
            for (int nt = 0; nt < 8; ++nt) {
                mma16816(acc[mt][nt], ahi[mt], bh[nt].x, bh[nt].y);
                mma16816(acc[mt][nt], alo[mt], bh[nt].x, bh[nt].y);
                mma16816(acc[mt][nt], ahi[mt], bl[nt].x, bl[nt].y);
            }
    }

    // ---- epilogue: bias + relu (+ dinv prescale for next layer) ----
    float dv[2][2];
    #pragma unroll
    for (int mt = 0; mt < 2; ++mt) {
        int r0 = mbase + mt * 16 + qrow;
        int r1 = r0 + 8;
        dv[mt][0] = write_internal ? ((r0 < NN) ? g_dinv[r0] : 0.0f) : 1.0f;
        dv[mt][1] = write_internal ? ((r1 < NN) ? g_dinv[r1] : 0.0f) : 1.0f;
    }
    #pragma unroll
    for (int nt = 0; nt < 8; ++nt) {
        int col = nbase + nt * 8 + qcol;
        float2 bb = *(const float2*)(bg + col);
        #pragma unroll
        for (int mt = 0; mt < 2; ++mt) {
            int r0 = mbase + mt * 16 + qrow;
            int r1 = r0 + 8;
            if (r0 < NN) {
                float2 o0;
                o0.x = fmaxf(acc[mt][nt][0] + bb.x, 0.0f) * dv[mt][0];
                o0.y = fmaxf(acc[mt][nt][1] + bb.y, 0.0f) * dv[mt][0];
                *(float2*)(outp + (size_t)r0 * DD + col) = o0;
            }
            if (r1 < NN) {
                float2 o1;
                o1.x = fmaxf(acc[mt][nt][2] + bb.x, 0.0f) * dv[mt][1];
                o1.y = fmaxf(acc[mt][nt][3] + bb.y, 0.0f) * dv[mt][1];
                *(float2*)(outp + (size_t)r1 * DD + col) = o1;
            }
        }
    }
}

// ---------------- launch ----------------------------------------------------
extern "C" void kernel_launch(void* const* d_in, const int* in_sizes, int n_in,
                              void* d_out, int out_size) {
    const float* x  = (const float*)d_in[0];
    const void*  ei = d_in[1];
    const float* W  = (const float*)d_in[2];
    const float* b  = (const float*)d_in[3];
    float* out = (float*)d_out;

    k_pre<<<(NN + 255) / 256, 256>>>((const int*)ei, W);
    k_deg<<<(EE + 255) / 256, 256>>>(ei);
    k_scan<<<1, 1024>>>();
    k_csr_scale<<<CSR_BLOCKS + SCALE_BLOCKS, 256>>>(ei, x);

    int aggGrid = (NN * 32 + 255) / 256;

    // layer 0
    k_agg<<<aggGrid, 256>>>(0);
    k_gemm_mma<<<TILES, 256>>>(b, out, 0, 1);

    // layer 1
    k_agg<<<aggGrid, 256>>>(1);
    k_gemm_mma<<<TILES, 256>>>(b + DD, out, 1, 0);
}

// round 5
// speedup vs baseline: 1.1165x; 1.1165x over previous
#include <cuda_runtime.h>
#include <cuda_bf16.h>
#include <cuda_fp16.h>
#include <cstdint>

#define NN 50000
#define EE 800000
#define DD 128
#define TILES ((NN + 127) / 128)       // 391
#define PADROWS (TILES * 128)          // 50048
#define CSR_BLOCKS ((EE + 255) / 256)  // 3125
#define SCALE_BLOCKS ((NN * 32 + 255) / 256)

// ---------------- scratch (static device globals; no allocation) ----------
__device__ __half   g_y16[NN * DD];     // y0 = dinv .* x   (fp16)
__device__ __half   g_h16[NN * DD];     // y1 = dinv .* relu(layer0) (fp16)
__device__ uint32_t g_ap[PADROWS * DD]; // agg out, packed bf16 (hi,lo)
__device__ int      g_csr_src[EE];
__device__ int      g_deg[NN];
__device__ int      g_off[NN + 1];
__device__ int      g_cur[NN];
__device__ float    g_dinv[NN];
__device__ int      g_is64;
// W packed in mma.m16n8k16 B-fragment order, bf16 hi/lo
__device__ uint32_t g_bp_hi[2 * 8 * 16 * 64];
__device__ uint32_t g_bp_lo[2 * 8 * 16 * 64];

// ---------------- fused: zero counters + dtype detect + W pack -------------
__global__ void k_pre(const int* __restrict__ raw, const float* __restrict__ W) {
    int idx = blockIdx.x * blockDim.x + threadIdx.x;
    if (idx < NN) { g_deg[idx] = 0; g_cur[idx] = 0; }
    if (idx < 2 * DD * DD) {
        int l = idx >> 14;
        int r = idx & 16383;
        int k = r >> 7;    // K index (in-dim)
        int n = r & 127;   // N index (out-dim)
        float v = W[l * DD * DD + k * DD + n];
        __nv_bfloat16 h  = __float2bfloat16(v);
        __nv_bfloat16 lo = __float2bfloat16(v - __bfloat162float(h));
        int ks = k >> 4, kk = k & 15;
        int reg = kk >> 3, k8 = kk & 7;
        int lane = ((n & 7) << 2) | (k8 >> 1);
        int i    = k8 & 1;
        int nt   = n >> 3;
        size_t u32i = ((((size_t)l * 8 + ks) * 16 + nt) * 64) + (size_t)lane * 2 + reg;
        ((unsigned short*)g_bp_hi)[u32i * 2 + i] = __bfloat16_as_ushort(h);
        ((unsigned short*)g_bp_lo)[u32i * 2 + i] = __bfloat16_as_ushort(lo);
    }
    if (blockIdx.x == 0) {
        __shared__ int found;
        if (threadIdx.x == 0) found = 0;
        __syncthreads();
        for (int j = threadIdx.x; j < 2048; j += blockDim.x)
            if (raw[2 * j + 1] != 0) found = 1;
        __syncthreads();
        if (threadIdx.x == 0) g_is64 = found ? 0 : 1;
    }
}

__device__ __forceinline__ void load_edge(const void* raw, int e, int is64,
                                          int& s, int& d) {
    if (is64) {
        const long long* p = (const long long*)raw;
        s = (int)p[e];
        d = (int)p[EE + e];
    } else {
        const int* p = (const int*)raw;
        s = p[e];
        d = p[EE + e];
    }
}

__global__ void k_deg(const void* __restrict__ raw) {
    int e = blockIdx.x * blockDim.x + threadIdx.x;
    if (e >= EE) return;
    int d;
    if (g_is64) d = (int)((const long long*)raw)[EE + e];
    else        d = ((const int*)raw)[EE + e];
    atomicAdd(&g_deg[d], 1);
}

// single-block scan of g_deg -> g_off; also computes g_dinv
__global__ void k_scan() {
    const int T = 1024;
    const int ITEMS = (NN + T - 1) / T;  // 49
    __shared__ int sm[T];
    int t = threadIdx.x;
    int base = t * ITEMS;
    int sum = 0;
    for (int j = 0; j < ITEMS; ++j) {
        int idx = base + j;
        if (idx < NN) sum += g_deg[idx];
    }
    sm[t] = sum;
    __syncthreads();
    for (int dstep = 1; dstep < T; dstep <<= 1) {
        int v = (t >= dstep) ? sm[t - dstep] : 0;
        __syncthreads();
        sm[t] += v;
        __syncthreads();
    }
    int run = sm[t] - sum;
    for (int j = 0; j < ITEMS; ++j) {
        int idx = base + j;
        if (idx < NN) {
            int dg = g_deg[idx];
            g_off[idx] = run;
            g_dinv[idx] = rsqrtf((float)dg + 1.0f);
            run += dg;
        }
    }
    if (t == T - 1) g_off[NN] = sm[T - 1];
}

// ---------------- fused: CSR scatter (src only) + y0 = fp16(dinv.*x) -------
__global__ void k_csr_scale(const void* __restrict__ raw,
                            const float* __restrict__ x) {
    int b = blockIdx.x;
    if (b < CSR_BLOCKS) {
        int e = b * 256 + threadIdx.x;
        if (e < EE) {
            int is64 = g_is64;
            int s, d;
            load_edge(raw, e, is64, s, d);
            int p = g_off[d] + atomicAdd(&g_cur[d], 1);
            g_csr_src[p] = s;
        }
    } else {
        int i = (b - CSR_BLOCKS) * 256 + threadIdx.x;
        if (i < NN * 32) {
            int row = i >> 5, l = i & 31;
            float di = g_dinv[row];
            float4 v = ((const float4*)(x + (size_t)row * DD))[l];
            __half2 h01 = __floats2half2_rn(v.x * di, v.y * di);
            __half2 h23 = __floats2half2_rn(v.z * di, v.w * di);
            uint2 o;
            o.x = *(uint32_t*)&h01;
            o.y = *(uint32_t*)&h23;
            *(uint2*)(g_y16 + (size_t)row * DD + 4 * l) = o;
        }
    }
}

// ---------------- aggregation: warp per node, fp16 gathers -----------------
// out[d] = dinv[d] * (y[d] + sum y[s]); writes packed bf16 (hi,lo) to g_ap
__global__ void k_agg(int use_internal) {
    int gw   = (blockIdx.x * blockDim.x + threadIdx.x) >> 5;
    int lane = threadIdx.x & 31;
    if (gw >= NN) return;
    const __half* __restrict__ y = use_internal ? g_h16 : g_y16;

    // self term
    float4 acc;
    {
        uint2 v = *(const uint2*)(y + (size_t)gw * DD + 4 * lane);
        float2 f01 = __half22float2(*(__half2*)&v.x);
        float2 f23 = __half22float2(*(__half2*)&v.y);
        acc = make_float4(f01.x, f01.y, f23.x, f23.y);
    }

    int beg = g_off[gw];
    int end = g_off[gw + 1];
    for (int e0 = beg; e0 < end; e0 += 32) {
        int m = end - e0;
        if (m > 32) m = 32;
        int s_all = (lane < m) ? g_csr_src[e0 + lane] : 0;
        int jb = 0;
        for (; jb + 8 <= m; jb += 8) {
            uint2 v[8];
            #pragma unroll
            for (int j = 0; j < 8; ++j) {
                int sj = __shfl_sync(0xffffffffu, s_all, jb + j);
                v[j] = *(const uint2*)(y + (size_t)sj * DD + 4 * lane);
            }
            #pragma unroll
            for (int j = 0; j < 8; ++j) {
                float2 f01 = __half22float2(*(__half2*)&v[j].x);
                float2 f23 = __half22float2(*(__half2*)&v[j].y);
                acc.x += f01.x; acc.y += f01.y;
                acc.z += f23.x; acc.w += f23.y;
            }
        }
        for (; jb < m; ++jb) {
            int sj = __shfl_sync(0xffffffffu, s_all, jb);
            uint2 v = *(const uint2*)(y + (size_t)sj * DD + 4 * lane);
            float2 f01 = __half22float2(*(__half2*)&v.x);
            float2 f23 = __half22float2(*(__half2*)&v.y);
            acc.x += f01.x; acc.y += f01.y;
            acc.z += f23.x; acc.w += f23.y;
        }
    }
    float di = g_dinv[gw];
    acc.x *= di; acc.y *= di; acc.z *= di; acc.w *= di;

    // pack to bf16 hi/lo, interleaved (hi, lo) per float-pair
    __nv_bfloat162 h01 = __floats2bfloat162_rn(acc.x, acc.y);
    __nv_bfloat162 h23 = __floats2bfloat162_rn(acc.z, acc.w);
    float rx = acc.x - __bfloat162float(__low2bfloat16(h01));
    float ry = acc.y - __bfloat162float(__high2bfloat16(h01));
    float rz = acc.z - __bfloat162float(__low2bfloat16(h23));
    float rw = acc.w - __bfloat162float(__high2bfloat16(h23));
    __nv_bfloat162 l01 = __floats2bfloat162_rn(rx, ry);
    __nv_bfloat162 l23 = __floats2bfloat162_rn(rz, rw);
    uint4 o;
    o.x = *(uint32_t*)&h01;
    o.y = *(uint32_t*)&l01;
    o.z = *(uint32_t*)&h23;
    o.w = *(uint32_t*)&l23;
    *(uint4*)(g_ap + (size_t)gw * DD + 4 * lane) = o;
}

// ---------------- mma.sync GEMM: out = relu(agg @ W + b) [, * dinv] --------
__device__ __forceinline__ void mma16816(float* d, const uint32_t* a,
                                         const uint32_t b0, const uint32_t b1) {
    asm volatile(
        "mma.sync.aligned.m16n8k16.row.col.f32.bf16.bf16.f32 "
        "{%0,%1,%2,%3}, {%4,%5,%6,%7}, {%8,%9}, {%0,%1,%2,%3};"
        : "+f"(d[0]), "+f"(d[1]), "+f"(d[2]), "+f"(d[3])
        : "r"(a[0]), "r"(a[1]), "r"(a[2]), "r"(a[3]), "r"(b0), "r"(b1));
}

__global__ void __launch_bounds__(256)
k_gemm_mma(const float* __restrict__ bg, float* __restrict__ outext,
           int layer, int write_internal) {
    int tid  = threadIdx.x;
    int lane = tid & 31;
    int wid  = tid >> 5;
    int mbase = blockIdx.x * 128 + (wid & 3) * 32;  // warp's 32 rows
    int nbase = (wid >> 2) * 64;                    // warp's 64 cols

    int qrow = lane >> 2;
    int qcol = (lane & 3) * 2;
    int q    = lane & 3;

    float acc[2][8][4];
    #pragma unroll
    for (int mt = 0; mt < 2; ++mt)
        #pragma unroll
        for (int nt = 0; nt < 8; ++nt)
            #pragma unroll
            for (int j = 0; j < 4; ++j) acc[mt][nt][j] = 0.0f;

    const uint2* __restrict__ ap   = (const uint2*)g_ap;
    const uint2* __restrict__ bhiP = (const uint2*)g_bp_hi;
    const uint2* __restrict__ bloP = (const uint2*)g_bp_lo;

    #pragma unroll 2
    for (int ks = 0; ks < 8; ++ks) {
        uint32_t ahi[2][4], alo[2][4];
        #pragma unroll
        for (int mt = 0; mt < 2; ++mt) {
            int r0 = mbase + mt * 16 + qrow;
            int r1 = r0 + 8;
            uint2 v00 = ap[(size_t)r0 * 64 + ks * 8 + q];
            uint2 v10 = ap[(size_t)r1 * 64 + ks * 8 + q];
            uint2 v01 = ap[(size_t)r0 * 64 + ks * 8 + 4 + q];
            uint2 v11 = ap[(size_t)r1 * 64 + ks * 8 + 4 + q];
            ahi[mt][0] = v00.x; alo[mt][0] = v00.y;
            ahi[mt][1] = v10.x; alo[mt][1] = v10.y;
            ahi[mt][2] = v01.x; alo[mt][2] = v01.y;
            ahi[mt][3] = v11.x; alo[mt][3] = v11.y;
        }
        int bbase = (((layer * 8 + ks) * 16 + (nbase >> 3)) * 32) + lane;
        uint2 bh[8], bl[8];
        #pragma unroll
        for (int nt = 0; nt < 8; ++nt) {
            bh[nt] = bhiP[bbase + nt * 32];
            bl[nt] = bloP[bbase + nt * 32];
        }
        #pragma unroll
        for (int mt = 0; mt < 2; ++mt)
            #pragma unroll
            for (int nt = 0; nt < 8; ++nt) {
                mma16816(acc[mt][nt], ahi[mt], bh[nt].x, bh[nt].y);
                mma16816(acc[mt][nt], alo[mt], bh[nt].x, bh[nt].y);
                mma16816(acc[mt][nt], ahi[mt], bl[nt].x, bl[nt].y);
            }
    }

    // ---- epilogue ----
    if (write_internal) {
        // h = fp16(dinv * relu(acc + b))
        float dv[2][2];
        #pragma unroll
        for (int mt = 0; mt < 2; ++mt) {
            int r0 = mbase + mt * 16 + qrow;
            int r1 = r0 + 8;
            dv[mt][0] = (r0 < NN) ? g_dinv[r0] : 0.0f;
            dv[mt][1] = (r1 < NN) ? g_dinv[r1] : 0.0f;
        }
        #pragma unroll
        for (int nt = 0; nt < 8; ++nt) {
            int col = nbase + nt * 8 + qcol;
            float2 bb = *(const float2*)(bg + col);
            #pragma unroll
            for (int mt = 0; mt < 2; ++mt) {
                int r0 = mbase + mt * 16 + qrow;
                int r1 = r0 + 8;
                if (r0 < NN) {
                    __half2 o = __floats2half2_rn(
                        fmaxf(acc[mt][nt][0] + bb.x, 0.0f) * dv[mt][0],
                        fmaxf(acc[mt][nt][1] + bb.y, 0.0f) * dv[mt][0]);
                    *(__half2*)(g_h16 + (size_t)r0 * DD + col) = o;
                }
                if (r1 < NN) {
                    __half2 o = __floats2half2_rn(
                        fmaxf(acc[mt][nt][2] + bb.x, 0.0f) * dv[mt][1],
                        fmaxf(acc[mt][nt][3] + bb.y, 0.0f) * dv[mt][1]);
                    *(__half2*)(g_h16 + (size_t)r1 * DD + col) = o;
                }
            }
        }
    } else {
        #pragma unroll
        for (int nt = 0; nt < 8; ++nt) {
            int col = nbase + nt * 8 + qcol;
            float2 bb = *(const float2*)(bg + col);
            #pragma unroll
            for (int mt = 0; mt < 2; ++mt) {
                int r0 = mbase + mt * 16 + qrow;
                int r1 = r0 + 8;
                if (r0 < NN) {
                    float2 o0;
                    o0.x = fmaxf(acc[mt][nt][0] + bb.x, 0.0f);
                    o0.y = fmaxf(acc[mt][nt][1] + bb.y, 0.0f);
                    *(float2*)(outext + (size_t)r0 * DD + col) = o0;
                }
                if (r1 < NN) {
                    float2 o1;
                    o1.x = fmaxf(acc[mt][nt][2] + bb.x, 0.0f);
                    o1.y = fmaxf(acc[mt][nt][3] + bb.y, 0.0f);
                    *(float2*)(outext + (size_t)r1 * DD + col) = o1;
                }
            }
        }
    }
}

// ---------------- launch ----------------------------------------------------
extern "C" void kernel_launch(void* const* d_in, const int* in_sizes, int n_in,
                              void* d_out, int out_size) {
    const float* x  = (const float*)d_in[0];
    const void*  ei = d_in[1];
    const float* W  = (const float*)d_in[2];
    const float* b  = (const float*)d_in[3];
    float* out = (float*)d_out;

    k_pre<<<(NN + 255) / 256, 256>>>((const int*)ei, W);
    k_deg<<<(EE + 255) / 256, 256>>>(ei);
    k_scan<<<1, 1024>>>();
    k_csr_scale<<<CSR_BLOCKS + SCALE_BLOCKS, 256>>>(ei, x);

    int aggGrid = (NN * 32 + 255) / 256;

    // layer 0
    k_agg<<<aggGrid, 256>>>(0);
    k_gemm_mma<<<TILES, 256>>>(b, out, 0, 1);

    // layer 1
    k_agg<<<aggGrid, 256>>>(1);
    k_gemm_mma<<<TILES, 256>>>(b + DD, out, 1, 0);
}